// round 2
// baseline (speedup 1.0000x reference)
#include <cuda_runtime.h>

#define NN 50000
#define FF 128
#define HH 128
#define EE 800000
#define BN_EPS 1e-5f

// ---------------- scratch (static device globals; no allocation allowed) ----
__device__ __align__(16) float g_xw[(size_t)NN * HH];   // feature @ weight
__device__ __align__(16) float g_agg[(size_t)NN * HH];  // segment-summed messages
__device__ __align__(16) float g_sum[HH];
__device__ __align__(16) float g_sumsq[HH];
__device__ __align__(16) float g_scale[HH];
__device__ __align__(16) float g_shift[HH];

// ---------------- zero agg + stats ------------------------------------------
__global__ __launch_bounds__(256) void zero_kernel() {
    const size_t total4 = (size_t)NN * HH / 4;
    float4 z = make_float4(0.f, 0.f, 0.f, 0.f);
    for (size_t i = (size_t)blockIdx.x * blockDim.x + threadIdx.x; i < total4;
         i += (size_t)gridDim.x * blockDim.x) {
        reinterpret_cast<float4*>(g_agg)[i] = z;
    }
    if (blockIdx.x == 0 && threadIdx.x < HH) {
        g_sum[threadIdx.x] = 0.f;
        g_sumsq[threadIdx.x] = 0.f;
    }
}

// ---------------- SGEMM: g_xw[M,H] = A[M,F] * B[F,H] -------------------------
// 128x128 block tile, BK=16, 256 threads, 8x8 per-thread microtile.
__global__ __launch_bounds__(256) void gemm_kernel(const float* __restrict__ A,
                                                   const float* __restrict__ B) {
    __shared__ float As[16][132];  // [k][m], padded
    __shared__ float Bs[16][132];  // [k][n], padded

    const int block_row = blockIdx.x * 128;
    const int tid = threadIdx.x;
    const int ty = tid >> 4;        // 0..15 -> row group
    const int tx = tid & 15;        // 0..15 -> col group

    const int la_row = tid >> 2;          // 0..63
    const int la_k   = (tid & 3) * 4;     // 0,4,8,12
    const int lb_row = tid >> 5;          // 0..7
    const int lb_col = (tid & 31) * 4;    // 0..124

    float acc[8][8];
#pragma unroll
    for (int i = 0; i < 8; i++)
#pragma unroll
        for (int j = 0; j < 8; j++) acc[i][j] = 0.f;

    for (int k0 = 0; k0 < FF; k0 += 16) {
#pragma unroll
        for (int p = 0; p < 2; p++) {
            int m = la_row + p * 64;
            int r = block_row + m;
            float4 v = make_float4(0.f, 0.f, 0.f, 0.f);
            if (r < NN) v = *reinterpret_cast<const float4*>(A + (size_t)r * FF + k0 + la_k);
            As[la_k + 0][m] = v.x;
            As[la_k + 1][m] = v.y;
            As[la_k + 2][m] = v.z;
            As[la_k + 3][m] = v.w;
        }
#pragma unroll
        for (int p = 0; p < 2; p++) {
            int kr = lb_row + p * 8;
            float4 v = *reinterpret_cast<const float4*>(B + (size_t)(k0 + kr) * HH + lb_col);
            *reinterpret_cast<float4*>(&Bs[kr][lb_col]) = v;
        }
        __syncthreads();

#pragma unroll
        for (int k = 0; k < 16; k++) {
            float a[8], b[8];
#pragma unroll
            for (int i = 0; i < 2; i++)
                *reinterpret_cast<float4*>(&a[i * 4]) =
                    *reinterpret_cast<const float4*>(&As[k][ty * 8 + i * 4]);
#pragma unroll
            for (int i = 0; i < 2; i++)
                *reinterpret_cast<float4*>(&b[i * 4]) =
                    *reinterpret_cast<const float4*>(&Bs[k][tx * 8 + i * 4]);
#pragma unroll
            for (int i = 0; i < 8; i++)
#pragma unroll
                for (int j = 0; j < 8; j++) acc[i][j] += a[i] * b[j];
        }
        __syncthreads();
    }

#pragma unroll
    for (int i = 0; i < 8; i++) {
        int r = block_row + ty * 8 + i;
        if (r < NN) {
#pragma unroll
            for (int j = 0; j < 2; j++)
                *reinterpret_cast<float4*>(g_xw + (size_t)r * HH + tx * 8 + j * 4) =
                    *reinterpret_cast<float4*>(&acc[i][j * 4]);
        }
    }
}

// ---------------- SpMM scatter: agg[row] += w * xw[col] ----------------------
// One warp per edge; each lane owns one float4 (32 lanes * 4 = 128 = H).
__global__ __launch_bounds__(256) void spmm_kernel(const float* __restrict__ ew,
                                                   const int* __restrict__ erow,
                                                   const int* __restrict__ ecol) {
    int e = (int)(((size_t)blockIdx.x * blockDim.x + threadIdx.x) >> 5);
    if (e >= EE) return;
    int lane = threadIdx.x & 31;
    int r = __ldg(erow + e);
    int c = __ldg(ecol + e);
    float w = __ldg(ew + e);

    float4 v = *reinterpret_cast<const float4*>(g_xw + (size_t)c * HH + lane * 4);
    v.x *= w; v.y *= w; v.z *= w; v.w *= w;

    float* dst = g_agg + (size_t)r * HH + lane * 4;
    asm volatile("red.global.add.v4.f32 [%0], {%1, %2, %3, %4};"
                 :: "l"(dst), "f"(v.x), "f"(v.y), "f"(v.z), "f"(v.w)
                 : "memory");
}

// ---------------- column stats over agg (mean/var; bias cancels in BN) -------
__global__ __launch_bounds__(256) void stats_kernel() {
    const int c4 = threadIdx.x & 31;     // which float4 column group
    const int rstep = threadIdx.x >> 5;  // 0..7 row phase
    const int rows_per_block = (NN + gridDim.x - 1) / gridDim.x;
    const int r0 = blockIdx.x * rows_per_block;
    const int r1 = min(NN, r0 + rows_per_block);

    float4 s = make_float4(0.f, 0.f, 0.f, 0.f);
    float4 q = make_float4(0.f, 0.f, 0.f, 0.f);
    for (int r = r0 + rstep; r < r1; r += 8) {
        float4 x = *reinterpret_cast<const float4*>(g_agg + (size_t)r * HH + c4 * 4);
        s.x += x.x; s.y += x.y; s.z += x.z; s.w += x.w;
        q.x += x.x * x.x; q.y += x.y * x.y; q.z += x.z * x.z; q.w += x.w * x.w;
    }

    __shared__ float4 sh_s[256];
    __shared__ float4 sh_q[256];
    sh_s[threadIdx.x] = s;
    sh_q[threadIdx.x] = q;
    __syncthreads();

    if (rstep == 0) {
        float4 S = sh_s[c4];
        float4 Q = sh_q[c4];
#pragma unroll
        for (int wphase = 1; wphase < 8; wphase++) {
            float4 a = sh_s[c4 + 32 * wphase];
            float4 b = sh_q[c4 + 32 * wphase];
            S.x += a.x; S.y += a.y; S.z += a.z; S.w += a.w;
            Q.x += b.x; Q.y += b.y; Q.z += b.z; Q.w += b.w;
        }
        atomicAdd(&g_sum[c4 * 4 + 0], S.x);
        atomicAdd(&g_sum[c4 * 4 + 1], S.y);
        atomicAdd(&g_sum[c4 * 4 + 2], S.z);
        atomicAdd(&g_sum[c4 * 4 + 3], S.w);
        atomicAdd(&g_sumsq[c4 * 4 + 0], Q.x);
        atomicAdd(&g_sumsq[c4 * 4 + 1], Q.y);
        atomicAdd(&g_sumsq[c4 * 4 + 2], Q.z);
        atomicAdd(&g_sumsq[c4 * 4 + 3], Q.w);
    }
}

// ---------------- fold mean/var/gamma/beta into per-column scale/shift -------
__global__ void colfix_kernel(const float* __restrict__ gamma,
                              const float* __restrict__ beta) {
    int h = threadIdx.x;
    float mean = g_sum[h] * (1.f / NN);
    float var = g_sumsq[h] * (1.f / NN) - mean * mean;
    float sc = gamma[h] * rsqrtf(var + BN_EPS);
    g_scale[h] = sc;
    g_shift[h] = beta[h] - mean * sc;
}

// ---------------- fused epilogue: out = feature + relu(agg*scale + shift) ----
__global__ __launch_bounds__(256) void finalize_kernel(const float* __restrict__ feature,
                                                       float* __restrict__ out) {
    size_t i = (size_t)blockIdx.x * blockDim.x + threadIdx.x;  // float4 index
    const size_t total4 = (size_t)NN * HH / 4;
    if (i >= total4) return;
    int c4 = (int)(i & 31);

    float4 a = reinterpret_cast<const float4*>(g_agg)[i];
    float4 f = reinterpret_cast<const float4*>(feature)[i];
    float4 sc = reinterpret_cast<const float4*>(g_scale)[c4];
    float4 sh = reinterpret_cast<const float4*>(g_shift)[c4];

    float4 o;
    o.x = f.x + fmaxf(0.f, a.x * sc.x + sh.x);
    o.y = f.y + fmaxf(0.f, a.y * sc.y + sh.y);
    o.z = f.z + fmaxf(0.f, a.z * sc.z + sh.z);
    o.w = f.w + fmaxf(0.f, a.w * sc.w + sh.w);
    reinterpret_cast<float4*>(out)[i] = o;
}

// ---------------- launch -----------------------------------------------------
extern "C" void kernel_launch(void* const* d_in, const int* in_sizes, int n_in,
                              void* d_out, int out_size) {
    const float* feature = (const float*)d_in[0];   // [N, F]
    const float* weight  = (const float*)d_in[1];   // [F, H]
    // d_in[2] = bias: cancels exactly inside BatchNorm -> unused
    const float* gamma   = (const float*)d_in[3];   // [H]
    const float* beta    = (const float*)d_in[4];   // [H]
    const float* ew      = (const float*)d_in[5];   // [E]
    const int*   erow    = (const int*)d_in[6];     // [E]
    const int*   ecol    = (const int*)d_in[7];     // [E]
    float* out = (float*)d_out;                     // [N, H]

    zero_kernel<<<2048, 256>>>();
    gemm_kernel<<<(NN + 127) / 128, 256>>>(feature, weight);
    spmm_kernel<<<(EE + 7) / 8, 256>>>(ew, erow, ecol);
    stats_kernel<<<296, 256>>>();
    colfix_kernel<<<1, HH>>>(gamma, beta);
    finalize_kernel<<<(int)(((size_t)NN * HH / 4 + 255) / 256), 256>>>(feature, out);
}